// round 10
// baseline (speedup 1.0000x reference)
#include <cuda_runtime.h>
#include <cuda_bf16.h>
#include <cstdint>

// GMM: out[m] = sum_n w[n]*coef*exp(-(|x|^2+|mu|^2-2 x.mu)/2)
// R9: int8 IMMA mma.sync.m16n8k32.s8 (s32 accum). On all prior arches IMMA
// k32 issues at the same rate as HMMA k16 (2x MAC rate); fp8 (R7) did not.
// Quantization q=round(16*v), dot=qq/256 -> exponent err ~0.3 (fp8-equivalent,
// which scored 1.2e-11). Epilogue ex2 predicated on arg>-126 (exact: ftz ex2
// returns 0 below that anyway). Prep kernels merged.

#define M_DIM 16384
#define N_DIM 8192
#define NCHUNK 64
#define NSTAGE 8
#define COEF 0.15915494309189535f          // 1/(2*pi)
#define KQ 0.005635527503472513f           // log2(e)/256
#define NHL (-0.72134752044448170368f)     // -0.5*log2(e)

// Pre-swizzled s8 panels: [block][128 rows][128B], 16KB/block.
// Within a row, 16B-chunk c sits at byte col (c*16) ^ ((row&7)<<4).
__device__ __align__(128) char g_x[(M_DIM / 128) * 16384];   // 2 MB
__device__ __align__(128) char g_m[(N_DIM / 128) * 16384];   // 1 MB
__device__ float g_ax[M_DIM];                // -0.5*log2e*|x_m|^2
__device__ __align__(16) float2 g_bw[N_DIM]; // (-0.5*log2e*|mu_n|^2, w_n*coef)

// ---------------- smem layout (bytes) ----------------
#define MB_S   0                             // 8 stage mbarriers (8B each)
#define MB_X   64
#define OFF_BW 128                           // 8 slots x 1024B
#define OFF_X  8320                          // x panel 16KB
#define OFF_M  24704                         // 8 stage bufs x 16KB
#define SMEM_BYTES (OFF_M + NSTAGE * 16384)  // 155776

// ---------------- helpers ----------------
__device__ __forceinline__ uint32_t smem_u32(const void* p) {
    uint32_t a;
    asm("{ .reg .u64 t; cvta.to.shared.u64 t, %1; cvt.u32.u64 %0, t; }" : "=r"(a) : "l"(p));
    return a;
}
__device__ __forceinline__ void mbar_init(uint32_t addr, uint32_t cnt) {
    asm volatile("mbarrier.init.shared.b64 [%0], %1;" :: "r"(addr), "r"(cnt) : "memory");
}
__device__ __forceinline__ void mbar_expect(uint32_t addr, uint32_t bytes) {
    asm volatile("mbarrier.arrive.expect_tx.shared.b64 _, [%0], %1;"
                 :: "r"(addr), "r"(bytes) : "memory");
}
__device__ __forceinline__ void mbar_wait(uint32_t addr, uint32_t parity) {
    asm volatile(
        "{\n\t.reg .pred P;\n"
        "WL_%=:\n\t"
        "mbarrier.try_wait.parity.shared.b64 P, [%0], %1;\n\t"
        "@!P bra WL_%=;\n\t}"
        :: "r"(addr), "r"(parity) : "memory");
}
__device__ __forceinline__ void bulk_g2s(uint32_t dst, const void* src,
                                         uint32_t bytes, uint32_t mbar) {
    asm volatile(
        "cp.async.bulk.shared::cluster.global.mbarrier::complete_tx::bytes "
        "[%0], [%1], %2, [%3];"
        :: "r"(dst), "l"(src), "r"(bytes), "r"(mbar) : "memory");
}
__device__ __forceinline__ void ldsm4(uint32_t& r0, uint32_t& r1, uint32_t& r2,
                                      uint32_t& r3, uint32_t addr) {
    asm volatile("ldmatrix.sync.aligned.m8n8.x4.shared.b16 {%0,%1,%2,%3}, [%4];"
                 : "=r"(r0), "=r"(r1), "=r"(r2), "=r"(r3) : "r"(addr));
}
__device__ __forceinline__ void mma_s8(int& c0, int& c1, int& c2, int& c3,
                                       uint32_t a0, uint32_t a1, uint32_t a2, uint32_t a3,
                                       uint32_t b0, uint32_t b1) {
    asm volatile(
        "mma.sync.aligned.m16n8k32.row.col.s32.s8.s8.s32 "
        "{%0,%1,%2,%3}, {%4,%5,%6,%7}, {%8,%9}, {%0,%1,%2,%3};"
        : "+r"(c0), "+r"(c1), "+r"(c2), "+r"(c3)
        : "r"(a0), "r"(a1), "r"(a2), "r"(a3), "r"(b0), "r"(b1));
}
__device__ __forceinline__ void mma_s8_z(int& c0, int& c1, int& c2, int& c3,
                                         uint32_t a0, uint32_t a1, uint32_t a2, uint32_t a3,
                                         uint32_t b0, uint32_t b1) {
    asm volatile(
        "mma.sync.aligned.m16n8k32.row.col.s32.s8.s8.s32 "
        "{%0,%1,%2,%3}, {%4,%5,%6,%7}, {%8,%9}, {%10,%10,%10,%10};"
        : "=r"(c0), "=r"(c1), "=r"(c2), "=r"(c3)
        : "r"(a0), "r"(a1), "r"(a2), "r"(a3), "r"(b0), "r"(b1), "r"(0));
}
// e = 2^arg if arg > -126 else 0 (exactly matches ex2.approx.ftz's flush)
__device__ __forceinline__ float ex2_pred(float arg) {
    float e = 0.f;
    asm("{\n\t.reg .pred p;\n\t"
        "setp.gt.f32 p, %1, 0fC2FC0000;\n\t"   // -126.0f
        "@p ex2.approx.ftz.f32 %0, %1;\n\t}"
        : "+f"(e) : "f"(arg));
    return e;
}

// ---------------- prologue: fp32 -> s8*16 (pre-swizzled), norms ----------------
__global__ void prep(const float* __restrict__ x, const float* __restrict__ means,
                     const float* __restrict__ w) {
    int gr = blockIdx.x * 8 + (threadIdx.x >> 5);
    int lane = threadIdx.x & 31;
    const bool is_x = gr < M_DIM;
    int row = is_x ? gr : gr - M_DIM;
    const float* src = (is_x ? x : means) + (size_t)row * 128;
    char* dstb = (is_x ? g_x : g_m) + (size_t)(row >> 7) * 16384;
    int r = row & 127;

    float4 v = reinterpret_cast<const float4*>(src)[lane];
    float s = v.x * v.x + v.y * v.y + v.z * v.z + v.w * v.w;
    int q0 = __float2int_rn(v.x * 16.f), q1 = __float2int_rn(v.y * 16.f);
    int q2 = __float2int_rn(v.z * 16.f), q3 = __float2int_rn(v.w * 16.f);
    uint32_t p = (uint32_t)(q0 & 0xff) | ((uint32_t)(q1 & 0xff) << 8)
               | ((uint32_t)(q2 & 0xff) << 16) | ((uint32_t)(q3 & 0xff) << 24);
    uint32_t off = (uint32_t)r * 128
                 + ((((uint32_t)lane >> 2) * 16) ^ (((uint32_t)r & 7) << 4))
                 + ((uint32_t)lane & 3) * 4;
    *reinterpret_cast<uint32_t*>(dstb + off) = p;
#pragma unroll
    for (int o = 16; o; o >>= 1) s += __shfl_down_sync(0xffffffffu, s, o);
    if (lane == 0) {
        if (is_x) g_ax[row] = NHL * s;
        else      g_bw[row] = make_float2(NHL * s, w[row] * COEF);
    }
}

// ---------------- main fused kernel ----------------
// 128 CTAs x 256 threads. Warp grid 4(m) x 2(n); warp tile 32m x 64n.
// Per chunk per warp: 4 k-steps (K=32) x 2 m-tiles x 8 n-tiles = 64 IMMAs.
__global__ __launch_bounds__(256, 1) void gmm_mma(float* __restrict__ out) {
    extern __shared__ char smem[];
    const uint32_t sb = smem_u32(smem);
    const int tid = threadIdx.x, wid = tid >> 5, lane = tid & 31;
    const int wm = wid >> 1, wn = wid & 1;
    const int m0 = blockIdx.x * 128;

    if (tid == 0) {
#pragma unroll
        for (int s = 0; s < NSTAGE; s++) mbar_init(sb + MB_S + s * 8, 1);
        mbar_init(sb + MB_X, 1);
    }
    __syncthreads();
    if (tid == 0) {
        mbar_expect(sb + MB_X, 16384);
        bulk_g2s(sb + OFF_X, g_x + (size_t)blockIdx.x * 16384, 16384, sb + MB_X);
#pragma unroll
        for (int s = 0; s < NSTAGE; s++) {
            mbar_expect(sb + MB_S + s * 8, 17408);
            bulk_g2s(sb + OFF_M + s * 16384, g_m + (size_t)s * 16384, 16384, sb + MB_S + s * 8);
            bulk_g2s(sb + OFF_BW + s * 1024, (const char*)g_bw + (size_t)s * 1024, 1024,
                     sb + MB_S + s * 8);
        }
    }

    float axv[4];
#pragma unroll
    for (int mt = 0; mt < 2; mt++)
#pragma unroll
        for (int h = 0; h < 2; h++)
            axv[mt * 2 + h] = g_ax[m0 + wm * 32 + mt * 16 + h * 8 + (lane >> 2)];

    float s[4] = {0.f, 0.f, 0.f, 0.f};

    // A ldmatrix addressing (b16 view of s8 rows, 128B rows, XOR swizzle)
    const uint32_t sx = (uint32_t)((lane & 7) << 4);
    const uint32_t h16 = (uint32_t)((lane >> 4) * 16);
    const uint32_t aLin = sb + OFF_X + (uint32_t)((wm * 32 + (lane & 15)) * 128);
    // B ldmatrix: one x4 covers 2 n-tiles x 2 k-halves of one k-step
    const uint32_t bRow = (uint32_t)(wn * 64 + (lane & 7) + ((lane >> 4) & 1) * 8);
    const uint32_t bCol16 = (uint32_t)(((lane >> 3) & 1) * 16);
    const uint32_t bsx = (uint32_t)((bRow & 7) << 4);

    mbar_wait(sb + MB_X, 0);

    // Preload all A fragments (x tile is chunk-invariant; 32 regs).
    uint32_t ah[4][2][4];
#pragma unroll
    for (int ks = 0; ks < 4; ks++) {
        const uint32_t ko = ((uint32_t)(ks * 32) + h16) ^ sx;
#pragma unroll
        for (int mt = 0; mt < 2; mt++)
            ldsm4(ah[ks][mt][0], ah[ks][mt][1], ah[ks][mt][2], ah[ks][mt][3],
                  aLin + (uint32_t)(mt * 2048) + ko);
    }

    for (int i = 0; i < NCHUNK; i++) {
        const int st = i & (NSTAGE - 1);
        mbar_wait(sb + MB_S + st * 8, (uint32_t)(i >> 3) & 1);

        int acc[64];
        const uint32_t pbBase = sb + OFF_M + st * 16384 + bRow * 128;
#pragma unroll
        for (int ks = 0; ks < 4; ks++) {
            const uint32_t ko = ((uint32_t)(ks * 32) + bCol16) ^ bsx;
            uint32_t bf[4][4];   // [npPair]{np lo16, np hi16, np+1 lo16, np+1 hi16}
#pragma unroll
            for (int pp = 0; pp < 4; pp++)
                ldsm4(bf[pp][0], bf[pp][1], bf[pp][2], bf[pp][3],
                      pbBase + (uint32_t)(pp * 2 * 8 * 128) + ko);
#pragma unroll
            for (int mt = 0; mt < 2; mt++)
#pragma unroll
                for (int pp = 0; pp < 4; pp++) {
#pragma unroll
                    for (int half = 0; half < 2; half++) {
                        const int np = pp * 2 + half;
                        int* c = &acc[(mt * 8 + np) * 4];
                        if (ks == 0)
                            mma_s8_z(c[0], c[1], c[2], c[3],
                                     ah[ks][mt][0], ah[ks][mt][1], ah[ks][mt][2], ah[ks][mt][3],
                                     bf[pp][half * 2], bf[pp][half * 2 + 1]);
                        else
                            mma_s8(c[0], c[1], c[2], c[3],
                                   ah[ks][mt][0], ah[ks][mt][1], ah[ks][mt][2], ah[ks][mt][3],
                                   bf[pp][half * 2], bf[pp][half * 2 + 1]);
                    }
                }
        }

        // all warps done reading stage st -> refill it, then epilogue under DMA
        __syncthreads();
        if (tid == 0 && i + NSTAGE < NCHUNK) {
            const int c = i + NSTAGE;
            const uint32_t mb = sb + MB_S + st * 8;
            mbar_expect(mb, 17408);
            bulk_g2s(sb + OFF_M + st * 16384, g_m + (size_t)c * 16384, 16384, mb);
            bulk_g2s(sb + OFF_BW + st * 1024, (const char*)g_bw + (size_t)c * 1024, 1024, mb);
        }

        // fused epilogue: arg = (log2e/256)*dotq + ax + bn ; s += w * 2^arg
        const float4* bwp = reinterpret_cast<const float4*>(smem + OFF_BW + st * 1024);
#pragma unroll
        for (int nt = 0; nt < 8; nt++) {
            float4 bw4 = bwp[wn * 32 + nt * 4 + (lane & 3)];
#pragma unroll
            for (int mt = 0; mt < 2; mt++)
#pragma unroll
                for (int h = 0; h < 2; h++) {
                    float d0 = (float)acc[(mt * 8 + nt) * 4 + h * 2];
                    float d1 = (float)acc[(mt * 8 + nt) * 4 + h * 2 + 1];
                    float base = axv[mt * 2 + h];
                    float e0 = ex2_pred(fmaf(KQ, d0, base + bw4.x));
                    float e1 = ex2_pred(fmaf(KQ, d1, base + bw4.z));
                    s[mt * 2 + h] = fmaf(bw4.y, e0, s[mt * 2 + h]);
                    s[mt * 2 + h] = fmaf(bw4.w, e1, s[mt * 2 + h]);
                }
        }
    }

    // reduce: quad lanes (cols) -> smem (2 n-warps) -> out
#pragma unroll
    for (int k = 0; k < 4; k++) {
        s[k] += __shfl_xor_sync(0xffffffffu, s[k], 1);
        s[k] += __shfl_xor_sync(0xffffffffu, s[k], 2);
    }
    float* red = reinterpret_cast<float*>(smem + OFF_X);
    __syncthreads();
    if ((lane & 3) == 0) {
#pragma unroll
        for (int mt = 0; mt < 2; mt++)
#pragma unroll
            for (int h = 0; h < 2; h++) {
                int row = wm * 32 + mt * 16 + h * 8 + (lane >> 2);
                red[row * 2 + wn] = s[mt * 2 + h];
            }
    }
    __syncthreads();
    if (tid < 128) out[m0 + tid] = red[tid * 2] + red[tid * 2 + 1];
}

// ---------------------------------------------------------------------------
extern "C" void kernel_launch(void* const* d_in, const int* in_sizes, int n_in,
                              void* d_out, int out_size) {
    const float* x = (const float*)d_in[0];      // [16384, 128]
    const float* means = (const float*)d_in[1];  // [8192, 128]
    const float* w = (const float*)d_in[2];      // [8192]
    float* out = (float*)d_out;                  // [16384]
    (void)in_sizes; (void)n_in; (void)out_size;

    cudaFuncSetAttribute(gmm_mma, cudaFuncAttributeMaxDynamicSharedMemorySize, SMEM_BYTES);

    prep<<<(M_DIM + N_DIM) / 8, 256>>>(x, means, w);
    gmm_mma<<<128, 256, SMEM_BYTES>>>(out);
}

// round 12
// speedup vs baseline: 2.6259x; 2.6259x over previous
#include <cuda_runtime.h>
#include <cuda_bf16.h>
#include <cstdint>

// GMM: out[m] = sum_n w[n]*coef*exp(-(|x|^2+|mu|^2-2 x.mu)/2)
// R11: bf16 single-segment GEMM (R6 structure, fastest dtype on the legacy
// HMMA path: ~12cyc vs fp8 ~27, s8 ~50). New: merged prep kernel, predicated
// ex2, and half-chunk software pipelining — epilogue of each n-half is
// interleaved into the NEXT MMA phase's issue shadow (deferred across the
// chunk boundary via register-staged bw), targeting ~97% tensor-pipe util.

#define M_DIM 16384
#define N_DIM 8192
#define NCHUNK 64
#define NSTAGE 4
#define COEF 0.15915494309189535f          // 1/(2*pi)
#define LOG2E_F 1.4426950408889634f
#define NHL (-0.72134752044448170368f)     // -0.5*log2(e)

// Pre-swizzled bf16 panels: [block][128 rows][256B], 32KB/block.
// Within a row, 16B-chunk c sits at byte col (c*16) ^ ((row&7)<<4).
__device__ __align__(128) char g_x[(M_DIM / 128) * 32768];   // 4 MB
__device__ __align__(128) char g_m[(N_DIM / 128) * 32768];   // 2 MB
__device__ float g_ax[M_DIM];                // -0.5*log2e*|x_m|^2
__device__ __align__(16) float2 g_bw[N_DIM]; // (-0.5*log2e*|mu_n|^2, w_n*coef)

// ---------------- smem layout (bytes) ----------------
#define MB_S   0                             // 4 stage mbarriers (8B each)
#define MB_X   32
#define OFF_BW 64                            // 4 slots x 1024B
#define OFF_X  5120                          // x panel 32KB
#define OFF_M  38912                         // 4 stage bufs x 32KB
#define SMEM_BYTES (OFF_M + NSTAGE * 32768)  // 169984

// ---------------- helpers ----------------
__device__ __forceinline__ uint32_t smem_u32(const void* p) {
    uint32_t a;
    asm("{ .reg .u64 t; cvta.to.shared.u64 t, %1; cvt.u32.u64 %0, t; }" : "=r"(a) : "l"(p));
    return a;
}
__device__ __forceinline__ void mbar_init(uint32_t addr, uint32_t cnt) {
    asm volatile("mbarrier.init.shared.b64 [%0], %1;" :: "r"(addr), "r"(cnt) : "memory");
}
__device__ __forceinline__ void mbar_expect(uint32_t addr, uint32_t bytes) {
    asm volatile("mbarrier.arrive.expect_tx.shared.b64 _, [%0], %1;"
                 :: "r"(addr), "r"(bytes) : "memory");
}
__device__ __forceinline__ void mbar_wait(uint32_t addr, uint32_t parity) {
    asm volatile(
        "{\n\t.reg .pred P;\n"
        "WL_%=:\n\t"
        "mbarrier.try_wait.parity.shared.b64 P, [%0], %1;\n\t"
        "@!P bra WL_%=;\n\t}"
        :: "r"(addr), "r"(parity) : "memory");
}
__device__ __forceinline__ void bulk_g2s(uint32_t dst, const void* src,
                                         uint32_t bytes, uint32_t mbar) {
    asm volatile(
        "cp.async.bulk.shared::cluster.global.mbarrier::complete_tx::bytes "
        "[%0], [%1], %2, [%3];"
        :: "r"(dst), "l"(src), "r"(bytes), "r"(mbar) : "memory");
}
__device__ __forceinline__ void ldsm4(uint32_t& r0, uint32_t& r1, uint32_t& r2,
                                      uint32_t& r3, uint32_t addr) {
    asm volatile("ldmatrix.sync.aligned.m8n8.x4.shared.b16 {%0,%1,%2,%3}, [%4];"
                 : "=r"(r0), "=r"(r1), "=r"(r2), "=r"(r3) : "r"(addr));
}
__device__ __forceinline__ void mma16816(float& c0, float& c1, float& c2, float& c3,
                                         uint32_t a0, uint32_t a1, uint32_t a2, uint32_t a3,
                                         uint32_t b0, uint32_t b1) {
    asm volatile(
        "mma.sync.aligned.m16n8k16.row.col.f32.bf16.bf16.f32 "
        "{%0,%1,%2,%3}, {%4,%5,%6,%7}, {%8,%9}, {%0,%1,%2,%3};"
        : "+f"(c0), "+f"(c1), "+f"(c2), "+f"(c3)
        : "r"(a0), "r"(a1), "r"(a2), "r"(a3), "r"(b0), "r"(b1));
}
__device__ __forceinline__ void mma16816_z(float& c0, float& c1, float& c2, float& c3,
                                           uint32_t a0, uint32_t a1, uint32_t a2, uint32_t a3,
                                           uint32_t b0, uint32_t b1) {
    asm volatile(
        "mma.sync.aligned.m16n8k16.row.col.f32.bf16.bf16.f32 "
        "{%0,%1,%2,%3}, {%4,%5,%6,%7}, {%8,%9}, {%10,%10,%10,%10};"
        : "=f"(c0), "=f"(c1), "=f"(c2), "=f"(c3)
        : "r"(a0), "r"(a1), "r"(a2), "r"(a3), "r"(b0), "r"(b1), "f"(0.f));
}
// e = 2^arg if arg > -126 else 0 (exactly matches ex2.approx.ftz's flush-to-0)
__device__ __forceinline__ float ex2_pred(float arg) {
    float e = 0.f;
    asm("{\n\t.reg .pred p;\n\t"
        "setp.gt.f32 p, %1, 0fC2FC0000;\n\t"
        "@p ex2.approx.ftz.f32 %0, %1;\n\t}"
        : "+f"(e) : "f"(arg));
    return e;
}
__device__ __forceinline__ uint32_t pkbf(__nv_bfloat16 a, __nv_bfloat16 b) {
    __nv_bfloat162 t(a, b);
    return *reinterpret_cast<uint32_t*>(&t);
}

// ---------------- merged prologue: fp32 -> bf16 (pre-swizzled), norms --------
__global__ void prep(const float* __restrict__ x, const float* __restrict__ means,
                     const float* __restrict__ w) {
    int gr = blockIdx.x * 8 + (threadIdx.x >> 5);
    int lane = threadIdx.x & 31;
    const bool is_x = gr < M_DIM;
    int row = is_x ? gr : gr - M_DIM;
    const float* src = (is_x ? x : means) + (size_t)row * 128;
    char* dstb = (is_x ? g_x : g_m) + (size_t)(row >> 7) * 32768;
    int r = row & 127;

    float4 v = reinterpret_cast<const float4*>(src)[lane];
    float s = v.x * v.x + v.y * v.y + v.z * v.z + v.w * v.w;
    uint2 hv = make_uint2(pkbf(__float2bfloat16_rn(v.x), __float2bfloat16_rn(v.y)),
                          pkbf(__float2bfloat16_rn(v.z), __float2bfloat16_rn(v.w)));
    uint32_t off = (uint32_t)r * 256
                 + (((uint32_t)(lane >> 1) * 16) ^ (((uint32_t)r & 7) << 4))
                 + (uint32_t)(lane & 1) * 8;
    *reinterpret_cast<uint2*>(dstb + off) = hv;
#pragma unroll
    for (int o = 16; o; o >>= 1) s += __shfl_down_sync(0xffffffffu, s, o);
    if (lane == 0) {
        if (is_x) g_ax[row] = NHL * s;
        else      g_bw[row] = make_float2(NHL * s, w[row] * COEF);
    }
}

// ---------------- main fused kernel ----------------
// 128 CTAs x 256 threads. Warp grid 4(m) x 2(n); warp tile 32m x 64n.
// Each chunk split into two n-halves (np {0,1} / {2,3}); epilogue of a half is
// issued alongside the NEXT half's MMAs so MUFU/FMA hide in the HMMA shadow.
__global__ __launch_bounds__(256, 1) void gmm_mma(float* __restrict__ out) {
    extern __shared__ char smem[];
    const uint32_t sb = smem_u32(smem);
    const int tid = threadIdx.x, wid = tid >> 5, lane = tid & 31;
    const int wm = wid >> 1, wn = wid & 1;
    const int m0 = blockIdx.x * 128;

    if (tid == 0) {
#pragma unroll
        for (int s = 0; s < NSTAGE; s++) mbar_init(sb + MB_S + s * 8, 1);
        mbar_init(sb + MB_X, 1);
    }
    __syncthreads();
    if (tid == 0) {
        mbar_expect(sb + MB_X, 32768);
        bulk_g2s(sb + OFF_X, g_x + (size_t)blockIdx.x * 32768, 32768, sb + MB_X);
#pragma unroll
        for (int s = 0; s < NSTAGE; s++) {
            mbar_expect(sb + MB_S + s * 8, 33792);
            bulk_g2s(sb + OFF_M + s * 32768, g_m + (size_t)s * 32768, 32768, sb + MB_S + s * 8);
            bulk_g2s(sb + OFF_BW + s * 1024, (const char*)g_bw + (size_t)s * 1024, 1024,
                     sb + MB_S + s * 8);
        }
    }

    float axv[4];
#pragma unroll
    for (int mt = 0; mt < 2; mt++)
#pragma unroll
        for (int h = 0; h < 2; h++)
            axv[mt * 2 + h] = g_ax[m0 + wm * 32 + mt * 16 + h * 8 + (lane >> 2)];

    float s[4] = {0.f, 0.f, 0.f, 0.f};

    const uint32_t sx = (uint32_t)((lane & 7) << 4);
    const uint32_t h16 = (uint32_t)((lane >> 4) * 16);
    const uint32_t aLin = sb + OFF_X + (uint32_t)((wm * 32 + (lane & 15)) * 256);
    const uint32_t bLin = (uint32_t)((wn * 64 + (lane & 15)) * 256);
    const int bwIdx = wn * 32 + (lane & 3);

    mbar_wait(sb + MB_X, 0);

    // Preload all A fragments (x tile is chunk-invariant; 64 regs).
    uint32_t ah[8][2][4];
#pragma unroll
    for (int ks = 0; ks < 8; ks++) {
        const uint32_t ko = ((uint32_t)(ks * 32) + h16) ^ sx;
#pragma unroll
        for (int mt = 0; mt < 2; mt++)
            ldsm4(ah[ks][mt][0], ah[ks][mt][1], ah[ks][mt][2], ah[ks][mt][3],
                  aLin + (uint32_t)(mt * 4096) + ko);
    }

    // Half-MMA: np pair {h*2, h*2+1}, 64 MMAs, acc[mt][ntLocal(0..3)][4]
#define MMA_HALF(ACC, PB, HOFF)                                                   \
    {                                                                             \
        _Pragma("unroll")                                                         \
        for (int ks = 0; ks < 8; ks++) {                                          \
            const uint32_t ko = ((uint32_t)(ks * 32) + h16) ^ sx;                 \
            uint32_t bf[2][4];                                                    \
            _Pragma("unroll")                                                     \
            for (int npl = 0; npl < 2; npl++)                                     \
                ldsm4(bf[npl][0], bf[npl][1], bf[npl][2], bf[npl][3],             \
                      (PB) + (uint32_t)(((HOFF) * 2 + npl) * 4096) + ko);         \
            _Pragma("unroll")                                                     \
            for (int mt = 0; mt < 2; mt++)                                        \
                _Pragma("unroll")                                                 \
                for (int npl = 0; npl < 2; npl++) {                               \
                    float* c0 = &(ACC)[(mt * 4 + npl * 2) * 4];                   \
                    float* c1 = &(ACC)[(mt * 4 + npl * 2 + 1) * 4];               \
                    if (ks == 0) {                                                \
                        mma16816_z(c0[0], c0[1], c0[2], c0[3],                    \
                                   ah[ks][mt][0], ah[ks][mt][1],                  \
                                   ah[ks][mt][2], ah[ks][mt][3],                  \
                                   bf[npl][0], bf[npl][2]);                       \
                        mma16816_z(c1[0], c1[1], c1[2], c1[3],                    \
                                   ah[ks][mt][0], ah[ks][mt][1],                  \
                                   ah[ks][mt][2], ah[ks][mt][3],                  \
                                   bf[npl][1], bf[npl][3]);                       \
                    } else {                                                      \
                        mma16816(c0[0], c0[1], c0[2], c0[3],                      \
                                 ah[ks][mt][0], ah[ks][mt][1],                    \
                                 ah[ks][mt][2], ah[ks][mt][3],                    \
                                 bf[npl][0], bf[npl][2]);                         \
                        mma16816(c1[0], c1[1], c1[2], c1[3],                      \
                                 ah[ks][mt][0], ah[ks][mt][1],                    \
                                 ah[ks][mt][2], ah[ks][mt][3],                    \
                                 bf[npl][1], bf[npl][3]);                         \
                    }                                                             \
                }                                                                 \
        }                                                                         \
    }

    // Half-epilogue: 4 local n-tiles with register-staged bw
#define EPI_HALF(ACC, BW)                                                         \
    {                                                                             \
        _Pragma("unroll")                                                         \
        for (int ntl = 0; ntl < 4; ntl++) {                                       \
            float4 bw4 = (BW)[ntl];                                               \
            _Pragma("unroll")                                                     \
            for (int mt = 0; mt < 2; mt++)                                        \
                _Pragma("unroll")                                                 \
                for (int h = 0; h < 2; h++) {                                     \
                    float d0 = (ACC)[(mt * 4 + ntl) * 4 + h * 2];                 \
                    float d1 = (ACC)[(mt * 4 + ntl) * 4 + h * 2 + 1];             \
                    float base = axv[mt * 2 + h];                                 \
                    float e0 = ex2_pred(fmaf(LOG2E_F, d0, base + bw4.x));         \
                    float e1 = ex2_pred(fmaf(LOG2E_F, d1, base + bw4.z));         \
                    s[mt * 2 + h] = fmaf(bw4.y, e0, s[mt * 2 + h]);               \
                    s[mt * 2 + h] = fmaf(bw4.w, e1, s[mt * 2 + h]);               \
                }                                                                 \
        }                                                                         \
    }

    float acc0[32], acc1[32];
    float4 bwP[4];   // deferred half1 bw (staged before the barrier)

    for (int i = 0; i < NCHUNK; i++) {
        const int st = i & (NSTAGE - 1);
        mbar_wait(sb + MB_S + st * 8, (uint32_t)(i >> 2) & 1);

        const uint32_t pb = sb + OFF_M + st * 32768 + bLin;
        const float4* bwp = reinterpret_cast<const float4*>(smem + OFF_BW + st * 1024);

        // Phase A: MMAs for half0; deferred epilogue of prev chunk's half1
        // issues in the HMMA shadow.
        MMA_HALF(acc0, pb, 0);
        if (i > 0) EPI_HALF(acc1, bwP);

        // Phase B: MMAs for half1; epilogue of half0 in the shadow.
        float4 bwC[4];
#pragma unroll
        for (int j = 0; j < 4; j++) bwC[j] = bwp[bwIdx + j * 4];
        MMA_HALF(acc1, pb, 1);
        EPI_HALF(acc0, bwC);

        // Stage half1 bw to registers (smem slot gets recycled), then barrier.
#pragma unroll
        for (int j = 0; j < 4; j++) bwP[j] = bwp[bwIdx + (4 + j) * 4];

        __syncthreads();
        if (tid == 0 && i + NSTAGE < NCHUNK) {
            const int c = i + NSTAGE;
            const uint32_t mb = sb + MB_S + st * 8;
            mbar_expect(mb, 33792);
            bulk_g2s(sb + OFF_M + st * 32768, g_m + (size_t)c * 32768, 32768, mb);
            bulk_g2s(sb + OFF_BW + st * 1024, (const char*)g_bw + (size_t)c * 1024, 1024, mb);
        }
    }
    // Tail: last chunk's half1 epilogue
    EPI_HALF(acc1, bwP);

    // reduce: quad lanes (cols) -> smem (2 n-warps) -> out
#pragma unroll
    for (int k = 0; k < 4; k++) {
        s[k] += __shfl_xor_sync(0xffffffffu, s[k], 1);
        s[k] += __shfl_xor_sync(0xffffffffu, s[k], 2);
    }
    float* red = reinterpret_cast<float*>(smem + OFF_X);
    __syncthreads();
    if ((lane & 3) == 0) {
#pragma unroll
        for (int mt = 0; mt < 2; mt++)
#pragma unroll
            for (int h = 0; h < 2; h++) {
                int row = wm * 32 + mt * 16 + h * 8 + (lane >> 2);
                red[row * 2 + wn] = s[mt * 2 + h];
            }
    }
    __syncthreads();
    if (tid < 128) out[m0 + tid] = red[tid * 2] + red[tid * 2 + 1];
}

// ---------------------------------------------------------------------------
extern "C" void kernel_launch(void* const* d_in, const int* in_sizes, int n_in,
                              void* d_out, int out_size) {
    const float* x = (const float*)d_in[0];      // [16384, 128]
    const float* means = (const float*)d_in[1];  // [8192, 128]
    const float* w = (const float*)d_in[2];      // [8192]
    float* out = (float*)d_out;                  // [16384]
    (void)in_sizes; (void)n_in; (void)out_size;

    cudaFuncSetAttribute(gmm_mma, cudaFuncAttributeMaxDynamicSharedMemorySize, SMEM_BYTES);

    prep<<<(M_DIM + N_DIM) / 8, 256>>>(x, means, w);
    gmm_mma<<<128, 256, SMEM_BYTES>>>(out);
}